// round 6
// baseline (speedup 1.0000x reference)
#include <cuda_runtime.h>
#include <cstdint>

// ---------------------------------------------------------------------------
// Instant-NGP HashEncoder: B=2,097,152 points, D=3, L=16, C=2,
// base_res=16, desired=2048, log2_hashmap=19.
//
// R4: precomputed PAIR TABLE g_pair[i] = (e[i], e[i+1]) as float4.
// 16B entry stride -> every adjacent x-corner pair is ONE aligned LDG.128
// regardless of index parity (merge rate dense 50%->100%, hashed 25%->50%).
// Singles read 8B from the float2 view of the same table.
// 8 threads/point (2 levels each) -> fully coalesced float4 output stores.
// ---------------------------------------------------------------------------

#define NLEVELS 16
#define HASH_MASK 524287u
#define P2 2654435761u
#define P3 805459861u
#define TOTAL_PARAMS 6098120

// level tables (verified: total params == 6,098,120 matches reference)
__device__ const unsigned g_res[NLEVELS] = {16u, 23u, 31u, 43u, 59u, 81u, 112u, 154u,
                                            213u, 295u, 407u, 562u, 777u, 1073u, 1483u, 2048u};
__device__ const unsigned g_off[NLEVELS] = {0u, 4096u, 16264u, 46056u, 125568u,
                                            330952u, 855240u, 1379528u, 1903816u,
                                            2428104u, 2952392u, 3476680u, 4000968u,
                                            4525256u, 5049544u, 5573832u};
__device__ float g_scales[NLEVELS];

// pair table: g_pair[i] = (emb[i].x, emb[i].y, emb[i+1].x, emb[i+1].y)
__device__ float4 g_pair[TOTAL_PARAMS];

__global__ void init_scales_kernel() {
    int l = threadIdx.x;
    if (l < NLEVELS) {
        // match numpy: scale = exp2(l * log2(128)/15) * 16 - 1  (float64 -> float32)
        double s = exp2((double)l * (7.0 / 15.0)) * 16.0 - 1.0;
        g_scales[l] = (float)s;
    }
}

__global__ __launch_bounds__(256)
void build_pairs_kernel(const float2* __restrict__ emb) {
    int i = blockIdx.x * blockDim.x + threadIdx.x;
    if (i >= TOTAL_PARAMS) return;
    const float2 a = __ldg(&emb[i]);
    float2 b = make_float2(0.0f, 0.0f);
    if (i + 1 < TOTAL_PARAMS) b = __ldg(&emb[i + 1]);
    g_pair[i] = make_float4(a.x, a.y, b.x, b.y);
}

__device__ __forceinline__ void encode_level(int l, float x, float y, float z,
                                             float& ax, float& ay)
{
    const float scale = g_scales[l];
    const unsigned res = __ldg(&g_res[l]);
    const unsigned rm1 = res - 1u;
    const unsigned off = __ldg(&g_off[l]);

    const float px = __fadd_rn(__fmul_rn(x, scale), 0.5f);
    const float py = __fadd_rn(__fmul_rn(y, scale), 0.5f);
    const float pz = __fadd_rn(__fmul_rn(z, scale), 0.5f);

    const float fxg = floorf(px), fyg = floorf(py), fzg = floorf(pz);
    const float fx = px - fxg, fy = py - fyg, fz = pz - fzg;
    const unsigned gx = (unsigned)fxg, gy = (unsigned)fyg, gz = (unsigned)fzg;

    const float wx0 = 1.0f - fx, wx1 = fx;
    const float wy_[2] = {1.0f - fy, fy};
    const float wz_[2] = {1.0f - fz, fz};

    const unsigned cx0 = min(gx, rm1), cx1 = min(gx + 1u, rm1);
    const unsigned cy0 = min(gy, rm1), cy1 = min(gy + 1u, rm1);
    const unsigned cz0 = min(gz, rm1), cz1 = min(gz + 1u, rm1);

    // per-(y,z) global index pairs
    unsigned i0a[4], i1a[4];
    if (l >= 5) {
        const unsigned hy0 = cy0 * P2, hy1 = cy1 * P2;
        const unsigned hz0 = cz0 * P3, hz1 = cz1 * P3;
        const unsigned b0 = hy0 ^ hz0, b1 = hy1 ^ hz0, b2 = hy0 ^ hz1, b3 = hy1 ^ hz1;
        i0a[0] = ((cx0 ^ b0) & HASH_MASK) + off; i1a[0] = ((cx1 ^ b0) & HASH_MASK) + off;
        i0a[1] = ((cx0 ^ b1) & HASH_MASK) + off; i1a[1] = ((cx1 ^ b1) & HASH_MASK) + off;
        i0a[2] = ((cx0 ^ b2) & HASH_MASK) + off; i1a[2] = ((cx1 ^ b2) & HASH_MASK) + off;
        i0a[3] = ((cx0 ^ b3) & HASH_MASK) + off; i1a[3] = ((cx1 ^ b3) & HASH_MASK) + off;
    } else {
        const unsigned ry0 = cy0 * res, ry1 = cy1 * res;
        const unsigned rz0 = cz0 * res * res, rz1 = cz1 * res * res;
        const unsigned b0 = ry0 + rz0 + off, b1 = ry1 + rz0 + off;
        const unsigned b2 = ry0 + rz1 + off, b3 = ry1 + rz1 + off;
        i0a[0] = cx0 + b0; i1a[0] = cx1 + b0;
        i0a[1] = cx0 + b1; i1a[1] = cx1 + b1;
        i0a[2] = cx0 + b2; i1a[2] = cx1 + b2;
        i0a[3] = cx0 + b3; i1a[3] = cx1 + b3;
    }

    const float2* __restrict__ p2 = reinterpret_cast<const float2*>(g_pair);

    ax = 0.0f; ay = 0.0f;
#pragma unroll
    for (int p = 0; p < 4; ++p) {
        const unsigned by = p & 1u, bz = (p >> 1) & 1u;
        const float wyz = wy_[by] * wz_[bz];
        const float w0 = wx0 * wyz, w1 = wx1 * wyz;
        const unsigned i0 = i0a[p], i1 = i1a[p];

        if (i1 == i0 + 1u) {
            // adjacent pair: ONE aligned 16B load (pair table stride = 16B)
            const float4 q = __ldg(&g_pair[i0]);
            ax = fmaf(w0, q.x, ax);
            ay = fmaf(w0, q.y, ay);
            ax = fmaf(w1, q.z, ax);
            ay = fmaf(w1, q.w, ay);
        } else {
            // two 8B loads from the float2 view (first half of each pair entry)
            const float2 e0 = __ldg(&p2[2 * i0]);
            const float2 e1 = __ldg(&p2[2 * i1]);
            ax = fmaf(w0, e0.x, ax);
            ay = fmaf(w0, e0.y, ay);
            ax = fmaf(w1, e1.x, ax);
            ay = fmaf(w1, e1.y, ay);
        }
    }
}

__global__ __launch_bounds__(256)
void hash_encode_kernel8(const float* __restrict__ inputs,
                         float* __restrict__ out,
                         int B)
{
    const int t = blockIdx.x * blockDim.x + threadIdx.x;
    const int point = t >> 3;
    const int slot  = t & 7;
    if (point >= B) return;

    // 8 lanes per point read the same xyz -> warp-broadcast
    const float x = __ldg(&inputs[point * 3 + 0]);
    const float y = __ldg(&inputs[point * 3 + 1]);
    const float z = __ldg(&inputs[point * 3 + 2]);

    float a0x, a0y, a1x, a1y;
    encode_level(2 * slot + 0, x, y, z, a0x, a0y);
    encode_level(2 * slot + 1, x, y, z, a1x, a1y);

    // slot s writes floats [4s..4s+3] of the point's 32-float row:
    // warp covers 4 points -> 512B contiguous -> 4 lines per store instr
    float4* __restrict__ dst =
        reinterpret_cast<float4*>(out + (size_t)point * (2 * NLEVELS)) + slot;
    *dst = make_float4(a0x, a0y, a1x, a1y);
}

extern "C" void kernel_launch(void* const* d_in, const int* in_sizes, int n_in,
                              void* d_out, int out_size) {
    const float*  inputs = (const float*)d_in[0];   // [B, 3]
    const float2* emb    = (const float2*)d_in[1];  // [TOTAL_PARAMS, 2]
    float*        out    = (float*)d_out;           // [B, 32]

    const int B = in_sizes[0] / 3;

    init_scales_kernel<<<1, 32>>>();

    const int bthreads = 256;
    const int bblocks = (TOTAL_PARAMS + bthreads - 1) / bthreads;
    build_pairs_kernel<<<bblocks, bthreads>>>(emb);

    const int threads = 256;
    const long long total = (long long)B * 8;
    const int blocks = (int)((total + threads - 1) / threads);
    hash_encode_kernel8<<<blocks, threads>>>(inputs, out, B);
}

// round 12
// speedup vs baseline: 1.2439x; 1.2439x over previous
#include <cuda_runtime.h>
#include <cstdint>

// ---------------------------------------------------------------------------
// Instant-NGP HashEncoder: B=2,097,152 points, D=3, L=16, C=2,
// base_res=16, desired=2048, log2_hashmap=19.
//
// R10: dense-only pair table (levels 0..4, extent OFFSETS[5]=330,952 entries,
// 5.3 MB, L2-resident): every dense x-pair is one aligned LDG.128.
// Hashed levels (5..15): R3's EXACT merge rule (i1==i0+1 AND i0 even) — the
// parity check is required; XOR-adjacency does NOT imply even i0 (R9 bug).
// 8 threads/point (2 levels each) -> fully coalesced float4 output stores.
// ---------------------------------------------------------------------------

#define NLEVELS 16
#define HASH_MASK 524287u
#define P2 2654435761u
#define P3 805459861u
#define DENSE_PARAMS 330952   // OFFSETS[5]: total entries of dense levels 0..4

// level tables (verified: total params == 6,098,120 matches reference)
__device__ const unsigned g_res[NLEVELS] = {16u, 23u, 31u, 43u, 59u, 81u, 112u, 154u,
                                            213u, 295u, 407u, 562u, 777u, 1073u, 1483u, 2048u};
__device__ const unsigned g_off[NLEVELS] = {0u, 4096u, 16264u, 46056u, 125568u,
                                            330952u, 855240u, 1379528u, 1903816u,
                                            2428104u, 2952392u, 3476680u, 4000968u,
                                            4525256u, 5049544u, 5573832u};
__device__ float g_scales[NLEVELS];

// dense pair table: g_dpair[i] = (emb[i].x, emb[i].y, emb[i+1].x, emb[i+1].y)
__device__ float4 g_dpair[DENSE_PARAMS];

__global__ void init_scales_kernel() {
    int l = threadIdx.x;
    if (l < NLEVELS) {
        // match numpy: scale = exp2(l * log2(128)/15) * 16 - 1  (float64 -> float32)
        double s = exp2((double)l * (7.0 / 15.0)) * 16.0 - 1.0;
        g_scales[l] = (float)s;
    }
}

__global__ __launch_bounds__(256)
void build_dense_pairs_kernel(const float2* __restrict__ emb) {
    int i = blockIdx.x * blockDim.x + threadIdx.x;
    if (i >= DENSE_PARAMS) return;
    const float2 a = __ldg(&emb[i]);
    const float2 b = __ldg(&emb[i + 1]);   // i+1 <= DENSE_PARAMS < TOTAL, safe
    g_dpair[i] = make_float4(a.x, a.y, b.x, b.y);
}

__device__ __forceinline__ void encode_level(int l, float x, float y, float z,
                                             const float2* __restrict__ emb,
                                             float& ax, float& ay)
{
    const float scale = g_scales[l];
    const unsigned res = __ldg(&g_res[l]);
    const unsigned rm1 = res - 1u;
    const unsigned off = __ldg(&g_off[l]);

    const float px = __fadd_rn(__fmul_rn(x, scale), 0.5f);
    const float py = __fadd_rn(__fmul_rn(y, scale), 0.5f);
    const float pz = __fadd_rn(__fmul_rn(z, scale), 0.5f);

    const float fxg = floorf(px), fyg = floorf(py), fzg = floorf(pz);
    const float fx = px - fxg, fy = py - fyg, fz = pz - fzg;
    const unsigned gx = (unsigned)fxg, gy = (unsigned)fyg, gz = (unsigned)fzg;

    const float wx0 = 1.0f - fx, wx1 = fx;
    const float wy_[2] = {1.0f - fy, fy};
    const float wz_[2] = {1.0f - fz, fz};

    const unsigned cx0 = min(gx, rm1), cx1 = min(gx + 1u, rm1);
    const unsigned cy0 = min(gy, rm1), cy1 = min(gy + 1u, rm1);
    const unsigned cz0 = min(gz, rm1), cz1 = min(gz + 1u, rm1);

    ax = 0.0f; ay = 0.0f;

    if (l >= 5) {
        // ---- hashed level: R3 merge rule — adjacency AND even i0 required.
        // (XOR adjacency does NOT imply even parity: e.g. cx0=1,b=4 -> i0=5,i1=6.)
        const unsigned hy0 = cy0 * P2, hy1 = cy1 * P2;
        const unsigned hz0 = cz0 * P3, hz1 = cz1 * P3;
        const float2* __restrict__ tab = emb + off;
        const float4* __restrict__ tab4 = reinterpret_cast<const float4*>(tab);
        unsigned byz[4] = {hy0 ^ hz0, hy1 ^ hz0, hy0 ^ hz1, hy1 ^ hz1};
#pragma unroll
        for (int p = 0; p < 4; ++p) {
            const unsigned by = p & 1u, bz = (p >> 1) & 1u;
            const float wyz = wy_[by] * wz_[bz];
            const float w0 = wx0 * wyz, w1 = wx1 * wyz;
            const unsigned i0 = (cx0 ^ byz[p]) & HASH_MASK;
            const unsigned i1 = (cx1 ^ byz[p]) & HASH_MASK;
            if ((i1 == i0 + 1u) && !(i0 & 1u)) {
                // aligned adjacent pair -> one LDG.128
                const float4 q = __ldg(tab4 + (i0 >> 1));
                ax = fmaf(w0, q.x, ax);
                ay = fmaf(w0, q.y, ay);
                ax = fmaf(w1, q.z, ax);
                ay = fmaf(w1, q.w, ay);
            } else {
                const float2 e0 = __ldg(tab + i0);
                const float2 e1 = __ldg(tab + i1);
                ax = fmaf(w0, e0.x, ax);
                ay = fmaf(w0, e0.y, ay);
                ax = fmaf(w1, e1.x, ax);
                ay = fmaf(w1, e1.y, ay);
            }
        }
    } else {
        // ---- dense level: pair table -> 100% merge (any parity; x stride 1)
        const unsigned ry0 = cy0 * res, ry1 = cy1 * res;
        const unsigned rz0 = cz0 * res * res, rz1 = cz1 * res * res;
        const unsigned b0 = ry0 + rz0 + off, b1 = ry1 + rz0 + off;
        const unsigned b2 = ry0 + rz1 + off, b3 = ry1 + rz1 + off;
        unsigned bases[4] = {b0, b1, b2, b3};
        const bool noclamp = (cx1 == cx0 + 1u);
#pragma unroll
        for (int p = 0; p < 4; ++p) {
            const unsigned by = p & 1u, bz = (p >> 1) & 1u;
            const float wyz = wy_[by] * wz_[bz];
            const float w0 = wx0 * wyz, w1 = wx1 * wyz;
            const unsigned i0 = cx0 + bases[p];   // <= 330,946 < DENSE_PARAMS
            // one 16B load covers both x-corners: g_dpair[i0] = (emb[i0], emb[i0+1])
            const float4 q = __ldg(&g_dpair[i0]);
            if (noclamp) {
                ax = fmaf(w0, q.x, ax);
                ay = fmaf(w0, q.y, ay);
                ax = fmaf(w1, q.z, ax);
                ay = fmaf(w1, q.w, ay);
            } else {
                // x clamped: both corners are entry i0
                const float w = w0 + w1;
                ax = fmaf(w, q.x, ax);
                ay = fmaf(w, q.y, ay);
            }
        }
    }
}

__global__ __launch_bounds__(256)
void hash_encode_kernel8(const float* __restrict__ inputs,
                         const float2* __restrict__ emb,
                         float* __restrict__ out,
                         int B)
{
    const int t = blockIdx.x * blockDim.x + threadIdx.x;
    const int point = t >> 3;
    const int slot  = t & 7;
    if (point >= B) return;

    // 8 lanes per point read the same xyz -> warp-broadcast
    const float x = __ldg(&inputs[point * 3 + 0]);
    const float y = __ldg(&inputs[point * 3 + 1]);
    const float z = __ldg(&inputs[point * 3 + 2]);

    float a0x, a0y, a1x, a1y;
    encode_level(2 * slot + 0, x, y, z, emb, a0x, a0y);
    encode_level(2 * slot + 1, x, y, z, emb, a1x, a1y);

    // slot s writes floats [4s..4s+3] of the point's 32-float row:
    // warp covers 4 points -> 512B contiguous -> fully coalesced
    float4* __restrict__ dst =
        reinterpret_cast<float4*>(out + (size_t)point * (2 * NLEVELS)) + slot;
    *dst = make_float4(a0x, a0y, a1x, a1y);
}

extern "C" void kernel_launch(void* const* d_in, const int* in_sizes, int n_in,
                              void* d_out, int out_size) {
    const float*  inputs = (const float*)d_in[0];   // [B, 3]
    const float2* emb    = (const float2*)d_in[1];  // [TOTAL_PARAMS, 2]
    float*        out    = (float*)d_out;           // [B, 32]

    const int B = in_sizes[0] / 3;

    init_scales_kernel<<<1, 32>>>();

    const int bthreads = 256;
    const int bblocks = (DENSE_PARAMS + bthreads - 1) / bthreads;
    build_dense_pairs_kernel<<<bblocks, bthreads>>>(emb);

    const int threads = 256;
    const long long total = (long long)B * 8;
    const int blocks = (int)((total + threads - 1) / threads);
    hash_encode_kernel8<<<blocks, threads>>>(inputs, emb, out, B);
}

// round 13
// speedup vs baseline: 1.2918x; 1.0385x over previous
#include <cuda_runtime.h>
#include <cstdint>
#include <cmath>

// ---------------------------------------------------------------------------
// Instant-NGP HashEncoder: B=2,097,152 points, D=3, L=16, C=2,
// base_res=16, desired=2048, log2_hashmap=19.
//
// R13:
//  - Hashed levels: XOR-CHUNK merging. When cx0 is even, i1 = i0^1 exactly,
//    so both x-corners live in ONE aligned 16B chunk (i0>>1) whichever of
//    them is the even element. Test (i0^i1)==1, load one float4, select
//    halves by i0&1. Merge rate 25% -> 50%; lane-loads 97 -> 86 per point.
//  - Dense levels (0..4): pair table g_dpair (OFFSETS[5]=330,952 entries,
//    5.3MB, L2-resident), every dense x-pair is one LDG.128.
//  - Scales computed on HOST (float64 exp2 path == numpy) and passed by
//    value -> init kernel eliminated.
//  - 8 threads/point, 2 levels each -> fully coalesced float4 stores.
// ---------------------------------------------------------------------------

#define NLEVELS 16
#define HASH_MASK 524287u
#define P2 2654435761u
#define P3 805459861u
#define DENSE_PARAMS 330952   // OFFSETS[5]: total entries of dense levels 0..4

// level tables (verified: total params == 6,098,120 matches reference)
__device__ const unsigned g_res[NLEVELS] = {16u, 23u, 31u, 43u, 59u, 81u, 112u, 154u,
                                            213u, 295u, 407u, 562u, 777u, 1073u, 1483u, 2048u};
__device__ const unsigned g_off[NLEVELS] = {0u, 4096u, 16264u, 46056u, 125568u,
                                            330952u, 855240u, 1379528u, 1903816u,
                                            2428104u, 2952392u, 3476680u, 4000968u,
                                            4525256u, 5049544u, 5573832u};

struct Scales { float s[NLEVELS]; };

// dense pair table: g_dpair[i] = (emb[i].x, emb[i].y, emb[i+1].x, emb[i+1].y)
__device__ float4 g_dpair[DENSE_PARAMS];

__global__ __launch_bounds__(256)
void build_dense_pairs_kernel(const float2* __restrict__ emb) {
    int i = blockIdx.x * blockDim.x + threadIdx.x;
    if (i >= DENSE_PARAMS) return;
    const float2 a = __ldg(&emb[i]);
    const float2 b = __ldg(&emb[i + 1]);   // i+1 <= DENSE_PARAMS < TOTAL, safe
    g_dpair[i] = make_float4(a.x, a.y, b.x, b.y);
}

__device__ __forceinline__ void encode_level(int l, float scale,
                                             float x, float y, float z,
                                             const float2* __restrict__ emb,
                                             float& ax, float& ay)
{
    const unsigned res = __ldg(&g_res[l]);
    const unsigned rm1 = res - 1u;
    const unsigned off = __ldg(&g_off[l]);

    const float px = __fadd_rn(__fmul_rn(x, scale), 0.5f);
    const float py = __fadd_rn(__fmul_rn(y, scale), 0.5f);
    const float pz = __fadd_rn(__fmul_rn(z, scale), 0.5f);

    const float fxg = floorf(px), fyg = floorf(py), fzg = floorf(pz);
    const float fx = px - fxg, fy = py - fyg, fz = pz - fzg;
    const unsigned gx = (unsigned)fxg, gy = (unsigned)fyg, gz = (unsigned)fzg;

    const float wx0 = 1.0f - fx, wx1 = fx;
    const float wy_[2] = {1.0f - fy, fy};
    const float wz_[2] = {1.0f - fz, fz};

    const unsigned cx0 = min(gx, rm1), cx1 = min(gx + 1u, rm1);
    const unsigned cy0 = min(gy, rm1), cy1 = min(gy + 1u, rm1);
    const unsigned cz0 = min(gz, rm1), cz1 = min(gz + 1u, rm1);

    ax = 0.0f; ay = 0.0f;

    if (l >= 5) {
        // ---- hashed level: XOR-chunk merging.
        // If (i0^i1)==1, both corners are in the aligned 16B chunk i0>>1;
        // the half order depends on i0&1. Value-exact either way.
        const unsigned hy0 = cy0 * P2, hy1 = cy1 * P2;
        const unsigned hz0 = cz0 * P3, hz1 = cz1 * P3;
        const float2* __restrict__ tab = emb + off;
        const float4* __restrict__ tab4 = reinterpret_cast<const float4*>(tab);
        unsigned byz[4] = {hy0 ^ hz0, hy1 ^ hz0, hy0 ^ hz1, hy1 ^ hz1};
#pragma unroll
        for (int p = 0; p < 4; ++p) {
            const unsigned by = p & 1u, bz = (p >> 1) & 1u;
            const float wyz = wy_[by] * wz_[bz];
            const float w0 = wx0 * wyz, w1 = wx1 * wyz;
            const unsigned i0 = (cx0 ^ byz[p]) & HASH_MASK;
            const unsigned i1 = (cx1 ^ byz[p]) & HASH_MASK;
            if ((i0 ^ i1) == 1u) {
                // one aligned LDG.128 covers both corners
                const float4 q = __ldg(tab4 + (i0 >> 1));
                const bool sw = (i0 & 1u);          // i0 is the odd element?
                const float e0x = sw ? q.z : q.x;
                const float e0y = sw ? q.w : q.y;
                const float e1x = sw ? q.x : q.z;
                const float e1y = sw ? q.y : q.w;
                ax = fmaf(w0, e0x, ax);
                ay = fmaf(w0, e0y, ay);
                ax = fmaf(w1, e1x, ax);
                ay = fmaf(w1, e1y, ay);
            } else {
                const float2 e0 = __ldg(tab + i0);
                const float2 e1 = __ldg(tab + i1);
                ax = fmaf(w0, e0.x, ax);
                ay = fmaf(w0, e0.y, ay);
                ax = fmaf(w1, e1.x, ax);
                ay = fmaf(w1, e1.y, ay);
            }
        }
    } else {
        // ---- dense level: pair table -> 100% merge (any parity; x stride 1)
        const unsigned ry0 = cy0 * res, ry1 = cy1 * res;
        const unsigned rz0 = cz0 * res * res, rz1 = cz1 * res * res;
        const unsigned b0 = ry0 + rz0 + off, b1 = ry1 + rz0 + off;
        const unsigned b2 = ry0 + rz1 + off, b3 = ry1 + rz1 + off;
        unsigned bases[4] = {b0, b1, b2, b3};
        const bool noclamp = (cx1 == cx0 + 1u);
#pragma unroll
        for (int p = 0; p < 4; ++p) {
            const unsigned by = p & 1u, bz = (p >> 1) & 1u;
            const float wyz = wy_[by] * wz_[bz];
            const float w0 = wx0 * wyz, w1 = wx1 * wyz;
            const unsigned i0 = cx0 + bases[p];   // <= 330,946 < DENSE_PARAMS
            // one 16B load covers both x-corners: g_dpair[i0] = (emb[i0], emb[i0+1])
            const float4 q = __ldg(&g_dpair[i0]);
            if (noclamp) {
                ax = fmaf(w0, q.x, ax);
                ay = fmaf(w0, q.y, ay);
                ax = fmaf(w1, q.z, ax);
                ay = fmaf(w1, q.w, ay);
            } else {
                // x clamped: both corners are entry i0
                const float w = w0 + w1;
                ax = fmaf(w, q.x, ax);
                ay = fmaf(w, q.y, ay);
            }
        }
    }
}

__global__ __launch_bounds__(256)
void hash_encode_kernel8(const float* __restrict__ inputs,
                         const float2* __restrict__ emb,
                         float* __restrict__ out,
                         Scales sc,
                         int B)
{
    const int t = blockIdx.x * blockDim.x + threadIdx.x;
    const int point = t >> 3;
    const int slot  = t & 7;
    if (point >= B) return;

    // 8 lanes per point read the same xyz -> warp-broadcast
    const float x = __ldg(&inputs[point * 3 + 0]);
    const float y = __ldg(&inputs[point * 3 + 1]);
    const float z = __ldg(&inputs[point * 3 + 2]);

    const int l0 = 2 * slot;
    float a0x, a0y, a1x, a1y;
    encode_level(l0 + 0, sc.s[l0 + 0], x, y, z, emb, a0x, a0y);
    encode_level(l0 + 1, sc.s[l0 + 1], x, y, z, emb, a1x, a1y);

    // slot s writes floats [4s..4s+3] of the point's 32-float row:
    // warp covers 4 points -> 512B contiguous -> fully coalesced
    float4* __restrict__ dst =
        reinterpret_cast<float4*>(out + (size_t)point * (2 * NLEVELS)) + slot;
    *dst = make_float4(a0x, a0y, a1x, a1y);
}

extern "C" void kernel_launch(void* const* d_in, const int* in_sizes, int n_in,
                              void* d_out, int out_size) {
    const float*  inputs = (const float*)d_in[0];   // [B, 3]
    const float2* emb    = (const float2*)d_in[1];  // [TOTAL_PARAMS, 2]
    float*        out    = (float*)d_out;           // [B, 32]

    const int B = in_sizes[0] / 3;

    // scales on host: same float64 path as numpy (exp2(l*7/15)*16-1 -> f32)
    Scales sc;
    for (int l = 0; l < NLEVELS; ++l) {
        double s = exp2((double)l * (7.0 / 15.0)) * 16.0 - 1.0;
        sc.s[l] = (float)s;
    }

    const int bthreads = 256;
    const int bblocks = (DENSE_PARAMS + bthreads - 1) / bthreads;
    build_dense_pairs_kernel<<<bblocks, bthreads>>>(emb);

    const int threads = 256;
    const long long total = (long long)B * 8;
    const int blocks = (int)((total + threads - 1) / threads);
    hash_encode_kernel8<<<blocks, threads>>>(inputs, emb, out, sc, B);
}